// round 6
// baseline (speedup 1.0000x reference)
#include <cuda_runtime.h>
#include <cstdint>

typedef unsigned long long ull;

// Problem constants: B=32, L=256, C=16, D=128, char vocab = 128.
// out: float32 [2, 32, 128, 256]; out[0]=word conv, out[1]=char feats (transposed).

__device__ float g_Wt_word[3 * 128 * 128];  // [k][din][dout]
__device__ float g_Wt_chr [3 * 128 * 128];  // [k][din][dout]
__device__ float g_P      [128 * 3 * 128];  // [c][k][dout], bias folded into k=1

__device__ __forceinline__ void fma2(ull& d, ull a, ull b) {
    asm("fma.rn.f32x2 %0, %1, %2, %0;" : "+l"(d) : "l"(a), "l"(b));
}
__device__ __forceinline__ float2 up2(ull v) {
    float2 r;
    asm("mov.b64 {%0, %1}, %2;" : "=f"(r.x), "=f"(r.y) : "l"(v));
    return r;
}

// ---------------------------------------------------------------------------
// K1: transpose both conv weights [dout][din][k] -> [k][din][dout] in ONE
// launch. Blocks 0-95: word weights; blocks 96-191: char weights.
// ---------------------------------------------------------------------------
__global__ void k_trans(const float* __restrict__ ww, const float* __restrict__ wc) {
    int blk = blockIdx.x;
    const float* src = (blk < 96) ? ww : wc;
    float* dst = (blk < 96) ? g_Wt_word : g_Wt_chr;
    int o = ((blk < 96) ? blk : blk - 96) * 512 + threadIdx.x;  // 96*512 = 49152
    int k = o >> 14, r = o & 16383, din = r >> 7, dout = r & 127;
    dst[o] = src[dout * 384 + din * 3 + k];
}

// ---------------------------------------------------------------------------
// K2: P[c][k][dout] = sum_din chr_table[c,din] * w_chr[dout,din,k]  (+bias@k=1)
// 64 blocks x 256 threads; each block handles two c values.
// ---------------------------------------------------------------------------
__global__ void k_precomp(const float* __restrict__ chr_table,
                          const float* __restrict__ chr_b) {
    __shared__ float row[2][128];
    int c = blockIdx.x * 2 + (threadIdx.x >> 7);
    int d = threadIdx.x & 127;
    row[threadIdx.x >> 7][d] = chr_table[c * 128 + d];
    __syncthreads();
    const float* rw = row[threadIdx.x >> 7];
    float a0 = 0.f, a1 = 0.f, a2 = 0.f;
#pragma unroll 8
    for (int i = 0; i < 128; i++) {
        float e = rw[i];
        a0 = fmaf(e, g_Wt_chr[          i * 128 + d], a0);
        a1 = fmaf(e, g_Wt_chr[16384 +   i * 128 + d], a1);
        a2 = fmaf(e, g_Wt_chr[32768 +   i * 128 + d], a2);
    }
    g_P[(c * 3 + 0) * 128 + d] = a0;
    g_P[(c * 3 + 1) * 128 + d] = a1 + chr_b[d];
    g_P[(c * 3 + 2) * 128 + d] = a2;
}

// ---------------------------------------------------------------------------
// K3: char path. Block = (batch b, 64-token chunk). P in smem (192 KB).
// Warp handles 8 words; lane owns a dout-quad -> conflict-free LDS.128.
// ---------------------------------------------------------------------------
__global__ void k_char(const int* __restrict__ wic, float* __restrict__ out1) {
    extern __shared__ float sm[];
    float* Ps = sm;              // 49152 floats
    float* Fs = sm + 49152;      // 128 * 65 floats
    int tid = threadIdx.x;       // 256 threads
    int b  = blockIdx.x >> 2;
    int t0 = (blockIdx.x & 3) << 6;

    {   // load P into smem (L2-resident: 192 KB)
        const float4* src = (const float4*)g_P;
        float4* dst = (float4*)Ps;
#pragma unroll
        for (int i = 0; i < 48; i++) dst[tid + i * 256] = src[tid + i * 256];
    }
    __syncthreads();

    int warp = tid >> 5, lane = tid & 31;
    int d4 = lane << 2;

#define PL(cc, kk) (*(const float4*)&Ps[((cc) * 3 + (kk)) * 128 + d4])

    for (int ii = 0; ii < 8; ii++) {
        int lw = warp * 8 + ii;
        const int4* ip = (const int4*)(wic + (((b << 8) + t0 + lw) << 4));
        int4 q0 = ip[0], q1 = ip[1], q2 = ip[2], q3 = ip[3];
        int c[16] = {q0.x, q0.y, q0.z, q0.w, q1.x, q1.y, q1.z, q1.w,
                     q2.x, q2.y, q2.z, q2.w, q3.x, q3.y, q3.z, q3.w};

        float4 a = PL(c[0], 1);
        float4 r = PL(c[1], 2);
        float4 m;
        m.x = a.x + r.x; m.y = a.y + r.y; m.z = a.z + r.z; m.w = a.w + r.w;
#pragma unroll
        for (int t = 1; t < 15; t++) {
            float4 ce = PL(c[t], 1);
            float4 le = PL(c[t - 1], 0);
            float4 re = PL(c[t + 1], 2);
            float vx = ce.x + le.x + re.x;
            float vy = ce.y + le.y + re.y;
            float vz = ce.z + le.z + re.z;
            float vw = ce.w + le.w + re.w;
            m.x = fmaxf(m.x, vx); m.y = fmaxf(m.y, vy);
            m.z = fmaxf(m.z, vz); m.w = fmaxf(m.w, vw);
        }
        {
            float4 ce = PL(c[15], 1);
            float4 le = PL(c[14], 0);
            m.x = fmaxf(m.x, ce.x + le.x); m.y = fmaxf(m.y, ce.y + le.y);
            m.z = fmaxf(m.z, ce.z + le.z); m.w = fmaxf(m.w, ce.w + le.w);
        }
        Fs[(d4 + 0) * 65 + lw] = m.x;
        Fs[(d4 + 1) * 65 + lw] = m.y;
        Fs[(d4 + 2) * 65 + lw] = m.z;
        Fs[(d4 + 3) * 65 + lw] = m.w;
    }
#undef PL
    __syncthreads();

    int dout = tid >> 1;
    int half = tid & 1;
    const float* fsrc = Fs + dout * 65 + (half << 5);
    float* gdst = out1 + (((b << 7) + dout) << 8) + t0 + (half << 5);
#pragma unroll
    for (int i = 0; i < 8; i++) {
        float4 v = make_float4(fsrc[i * 4 + 0], fsrc[i * 4 + 1],
                               fsrc[i * 4 + 2], fsrc[i * 4 + 3]);
        ((float4*)gdst)[i] = v;
    }
}

// ---------------------------------------------------------------------------
// K4: word path GEMM with packed fp32x2 FMA.
// Block = (b, 64-token tile) x 128 dout, K = 3 taps x 128 din.
// Embedding tile stored DUPLICATED in smem: EsD[din][t] = (e_t, e_t) so the
// e operand of fma.rn.f32x2 needs no packing; the w operand comes straight
// out of smem as ulonglong2 (two natural f32x2 dout-pairs).
// Thread micro-tile: 8 tokens x 4 dout = 16 FFMA2 per din iteration.
// ---------------------------------------------------------------------------
#define CP16(dst_s, src_g) \
    asm volatile("cp.async.cg.shared.global [%0], [%1], 16;\n" :: "r"(dst_s), "l"(src_g))

#define ESPAD 67  // ull row stride for EsD (odd -> bounded STS conflicts)

// Shared memory byte budget (MUST be <= 232448 opt-in max on sm_103a):
//   EsD: 128 * ESPAD ull  = 128*67*8      = 68608 B
//   Ws : 2 * 16384 floats = 2*16384*4     = 131072 B
//   total                                  = 199680 B
#define SMEM_WORD_BYTES (128 * ESPAD * 8 + 2 * 16384 * 4)

__global__ void __launch_bounds__(256, 1)
k_word(const int* __restrict__ wv, const float* __restrict__ wtab,
       const float* __restrict__ wb, float* __restrict__ out0) {
    extern __shared__ float sm[];
    ull*   EsD = (ull*)sm;                  // 68608 B (dup e pairs)
    float* Ws  = sm + 2 * 128 * ESPAD;      // 131072 B (double-buffered tap)
    int tid = threadIdx.x;                  // 256 threads
    int b  = blockIdx.x >> 2;
    int t0 = (blockIdx.x & 3) << 6;

    unsigned ws_base = (unsigned)__cvta_generic_to_shared(Ws);
    {   // prefetch tap 0 weights into buffer 0
        const float* g0 = g_Wt_word;
#pragma unroll
        for (int i = 0; i < 16; i++) {
            int o4 = tid + i * 256;
            CP16(ws_base + o4 * 16, g0 + o4 * 4);
        }
        asm volatile("cp.async.commit_group;\n");
    }

    // Fill EsD: tokens v = 0..65 (global token t0+v-1), each din value stored
    // duplicated as a ull. Lane q loads dins {q, q+32, q+64, q+96} (coalesced).
    for (int item = tid; item < 66 * 32; item += 256) {
        int v = item >> 5, q = item & 31;
        int gt = t0 + v - 1;
        float e0 = 0.f, e1 = 0.f, e2 = 0.f, e3 = 0.f;
        if ((unsigned)gt < 256u) {
            int idx = __ldg(wv + (b << 8) + gt);
            const float* rp = wtab + idx * 128 + q;
            e0 = __ldg(rp); e1 = __ldg(rp + 32); e2 = __ldg(rp + 64); e3 = __ldg(rp + 96);
        }
        float2* Ef = (float2*)EsD;
        Ef[(q      ) * ESPAD + v] = make_float2(e0, e0);
        Ef[(q + 32 ) * ESPAD + v] = make_float2(e1, e1);
        Ef[(q + 64 ) * ESPAD + v] = make_float2(e2, e2);
        Ef[(q + 96 ) * ESPAD + v] = make_float2(e3, e3);
    }
    asm volatile("cp.async.wait_group 0;\n");
    __syncthreads();

    int row = tid >> 5, col = tid & 31;
    int tb = row << 3;                 // token base within tile
    ull acc[8][2];
#pragma unroll
    for (int i = 0; i < 8; i++) { acc[i][0] = 0ull; acc[i][1] = 0ull; }

#pragma unroll
    for (int tap = 0; tap < 3; tap++) {
        if (tap < 2) {  // prefetch next tap into the other buffer
            const float* gn = g_Wt_word + (tap + 1) * 16384;
            unsigned dstb = ws_base + (((tap + 1) & 1) * 16384) * 4;
#pragma unroll
            for (int i = 0; i < 16; i++) {
                int o4 = tid + i * 256;
                CP16(dstb + o4 * 16, gn + o4 * 4);
            }
            asm volatile("cp.async.commit_group;\n");
        }
        const ulonglong2* W2 = (const ulonglong2*)(Ws + (tap & 1) * 16384) + col;
        const ull* Eb = EsD + (tb + tap);
#pragma unroll 4
        for (int din = 0; din < 128; din++) {
            ulonglong2 w = W2[din * 32];        // douts (4c..4c+3) as two f32x2
#pragma unroll
            for (int i = 0; i < 8; i++) {
                ull e = Eb[din * ESPAD + i];    // (e, e) broadcast LDS.64
                fma2(acc[i][0], e, w.x);
                fma2(acc[i][1], e, w.y);
            }
        }
        if (tap < 2) {
            asm volatile("cp.async.wait_group 0;\n");
            __syncthreads();
        }
    }

    // epilogue: unpack halves, add bias, coalesced float4 stores along L
#pragma unroll
    for (int jp = 0; jp < 2; jp++) {
        int d0 = (col << 2) + jp * 2;
        float b0 = __ldg(wb + d0), b1 = __ldg(wb + d0 + 1);
        float v0[8], v1[8];
#pragma unroll
        for (int i = 0; i < 8; i++) {
            float2 u = up2(acc[i][jp]);
            v0[i] = u.x + b0;
            v1[i] = u.y + b1;
        }
        float* dA = out0 + (((b << 7) + d0    ) << 8) + t0 + tb;
        float* dB = out0 + (((b << 7) + d0 + 1) << 8) + t0 + tb;
        ((float4*)dA)[0] = make_float4(v0[0], v0[1], v0[2], v0[3]);
        ((float4*)dA)[1] = make_float4(v0[4], v0[5], v0[6], v0[7]);
        ((float4*)dB)[0] = make_float4(v1[0], v1[1], v1[2], v1[3]);
        ((float4*)dB)[1] = make_float4(v1[4], v1[5], v1[6], v1[7]);
    }
}

// ---------------------------------------------------------------------------
extern "C" void kernel_launch(void* const* d_in, const int* in_sizes, int n_in,
                              void* d_out, int out_size) {
    const int*   wv   = (const int*)d_in[0];    // word_vector  [32,256]
    const int*   wic  = (const int*)d_in[1];    // words_in_char [32,256,16]
    const float* wtab = (const float*)d_in[2];  // word_table [50000,128]
    const float* ctab = (const float*)d_in[3];  // chr_table [128,128]
    const float* wcw  = (const float*)d_in[4];  // conv_chr_w [128,128,3]
    const float* wcb  = (const float*)d_in[5];  // conv_chr_b [128]
    const float* www  = (const float*)d_in[6];  // conv_word_w [128,128,3]
    const float* wwb  = (const float*)d_in[7];  // conv_word_b [128]
    float* out  = (float*)d_out;
    float* out0 = out;                    // [32,128,256] word conv
    float* out1 = out + 32 * 128 * 256;   // [32,128,256] char feats

    const int SMEM_CHAR = 229888;            // 196608 (P) + 33280 (staging)
    const int SMEM_WORD = SMEM_WORD_BYTES;   // 68608 + 131072 = 199680
    cudaFuncSetAttribute(k_char, cudaFuncAttributeMaxDynamicSharedMemorySize, SMEM_CHAR);
    cudaFuncSetAttribute(k_word, cudaFuncAttributeMaxDynamicSharedMemorySize, SMEM_WORD);

    // Plain sequential launches only — graph-capture-safe.
    k_trans<<<192, 512>>>(www, wcw);
    k_precomp<<<64, 256>>>(ctab, wcb);
    k_char<<<128, 256, SMEM_CHAR>>>(wic, out1);
    k_word<<<128, 256, SMEM_WORD>>>(wv, wtab, wwb, out0);
}